// round 1
// baseline (speedup 1.0000x reference)
#include <cuda_runtime.h>
#include <cstdint>

#define NROWS 8192
#define DIM   16
#define NCT   64   // number of 128-wide column tiles

// ---- device scratch (static, no allocation) ----
__device__ float g_P1[NCT * NROWS];
__device__ float g_P2[NCT * NROWS];
__device__ float g_uX[NROWS];
__device__ float g_uR[NROWS];
__device__ float g_Dref[NROWS];
__device__ float g_bcol[NROWS];
__device__ float g_arow[NROWS];

__device__ __forceinline__ float ex2_approx(float x) {
    float r;
    asm("ex2.approx.f32 %0, %1;" : "=f"(r) : "f"(x));
    return r;
}

__device__ __forceinline__ float softplus_f(float x) {
    return log1pf(expf(x));
}

#define LOG2E 1.4426950408889634f

// ---------------------------------------------------------------------------
// k_prep: u[i] = -c2 * ||row_i||^2 for X and Xref, c2 = log2(e)/(4*eps)
// ---------------------------------------------------------------------------
__global__ void k_prep(const float* __restrict__ X,
                       const float* __restrict__ Xref,
                       const float* __restrict__ lep) {
    int i = blockIdx.x * blockDim.x + threadIdx.x;
    if (i >= NROWS) return;
    float eps = softplus_f(__ldg(lep));
    float c2 = LOG2E / (4.0f * eps);

    const float4* x4 = reinterpret_cast<const float4*>(X + (size_t)i * DIM);
    float s = 0.0f;
#pragma unroll
    for (int q = 0; q < 4; q++) {
        float4 v = x4[q];
        s += v.x * v.x + v.y * v.y + v.z * v.z + v.w * v.w;
    }
    g_uX[i] = -c2 * s;

    const float4* r4 = reinterpret_cast<const float4*>(Xref + (size_t)i * DIM);
    s = 0.0f;
#pragma unroll
    for (int q = 0; q < 4; q++) {
        float4 v = r4[q];
        s += v.x * v.x + v.y * v.y + v.z * v.z + v.w * v.w;
    }
    g_uR[i] = -c2 * s;
}

// ---------------------------------------------------------------------------
// k_eval: tiled RBF kernel evaluation. Computes K = exp(-d2 * inv_scale2)
// for a 128x128 tile, writes K to out, accumulates partial row sums:
//   P1[ct][row] = sum_j K          (this column tile)
//   P2[ct][row] = sum_j K*Dref[j]  (XPASS only)
// XPASS=false: A=B=Xref (u from g_uR both sides)
// XPASS=true : A=X, B=Xref (u from g_uX / g_uR), weighted sum with g_Dref
// ---------------------------------------------------------------------------
template <bool XPASS>
__global__ void __launch_bounds__(256, 2)
k_eval(const float* __restrict__ A,
       const float* __restrict__ B,
       const float* __restrict__ lep,
       float* __restrict__ out) {
    __shared__ float As[DIM][128];
    __shared__ float Bs[DIM][128];

    const int tid = threadIdx.x;
    const int tx = tid & 15;
    const int ty = tid >> 4;
    const int rb = blockIdx.y * 128;
    const int cb = blockIdx.x * 128;

    // ---- load tiles (k-major in smem) ----
    {
        int r = tid >> 1;          // 0..127
        int f = (tid & 1) * 2;     // float4 index 0 or 2
        const float4* ap = reinterpret_cast<const float4*>(A + (size_t)(rb + r) * DIM);
        const float4* bp = reinterpret_cast<const float4*>(B + (size_t)(cb + r) * DIM);
#pragma unroll
        for (int q = 0; q < 2; q++) {
            float4 va = ap[f + q];
            float4 vb = bp[f + q];
            int k0 = (f + q) * 4;
            As[k0 + 0][r] = va.x; As[k0 + 1][r] = va.y;
            As[k0 + 2][r] = va.z; As[k0 + 3][r] = va.w;
            Bs[k0 + 0][r] = vb.x; Bs[k0 + 1][r] = vb.y;
            Bs[k0 + 2][r] = vb.z; Bs[k0 + 3][r] = vb.w;
        }
    }
    __syncthreads();

    // ---- 8x8 register tile over full K=16 ----
    float acc[8][8];
#pragma unroll
    for (int i = 0; i < 8; i++)
#pragma unroll
        for (int j = 0; j < 8; j++) acc[i][j] = 0.0f;

#pragma unroll
    for (int k = 0; k < DIM; k++) {
        float4 a0 = *reinterpret_cast<const float4*>(&As[k][ty * 4]);
        float4 a1 = *reinterpret_cast<const float4*>(&As[k][64 + ty * 4]);
        float4 b0 = *reinterpret_cast<const float4*>(&Bs[k][tx * 4]);
        float4 b1 = *reinterpret_cast<const float4*>(&Bs[k][64 + tx * 4]);
        float av[8] = {a0.x, a0.y, a0.z, a0.w, a1.x, a1.y, a1.z, a1.w};
        float bv[8] = {b0.x, b0.y, b0.z, b0.w, b1.x, b1.y, b1.z, b1.w};
#pragma unroll
        for (int i = 0; i < 8; i++)
#pragma unroll
            for (int j = 0; j < 8; j++)
                acc[i][j] = fmaf(av[i], bv[j], acc[i][j]);
    }

    // ---- epilogue: K = exp2(min(2*c2*g + u_i + v_j, 0)) ----
    float eps = softplus_f(__ldg(lep));
    float twoc2 = 2.0f * (LOG2E / (4.0f * eps));

    int rows[8], cols[8];
    float u[8], v[8], w[8];
#pragma unroll
    for (int i = 0; i < 8; i++) {
        int m = (i < 4) ? (ty * 4 + i) : (64 + ty * 4 + (i - 4));
        rows[i] = rb + m;
        u[i] = (XPASS ? g_uX : g_uR)[rows[i]];
    }
#pragma unroll
    for (int j = 0; j < 8; j++) {
        int n = (j < 4) ? (tx * 4 + j) : (64 + tx * 4 + (j - 4));
        cols[j] = cb + n;
        v[j] = g_uR[cols[j]];
        if (XPASS) w[j] = g_Dref[cols[j]];
    }

    float s1[8], s2[8];
#pragma unroll
    for (int i = 0; i < 8; i++) { s1[i] = 0.0f; s2[i] = 0.0f; }

#pragma unroll
    for (int i = 0; i < 8; i++) {
#pragma unroll
        for (int j = 0; j < 8; j++) {
            float arg = fminf(fmaf(acc[i][j], twoc2, u[i] + v[j]), 0.0f);
            float kv = ex2_approx(arg);
            acc[i][j] = kv;
            s1[i] += kv;
            if (XPASS) s2[i] = fmaf(kv, w[j], s2[i]);
        }
    }

    // ---- reduce row sums across the 16 threads sharing each row ----
    // lanes with same ty occupy one half-warp; xor offsets <16 stay inside it
#pragma unroll
    for (int i = 0; i < 8; i++) {
        float t1 = s1[i];
        float t2 = XPASS ? s2[i] : 0.0f;
#pragma unroll
        for (int off = 8; off >= 1; off >>= 1) {
            t1 += __shfl_xor_sync(0xffffffffu, t1, off);
            if (XPASS) t2 += __shfl_xor_sync(0xffffffffu, t2, off);
        }
        if (tx == 0) {
            g_P1[(size_t)blockIdx.x * NROWS + rows[i]] = t1;
            if (XPASS) g_P2[(size_t)blockIdx.x * NROWS + rows[i]] = t2;
        }
    }

    // ---- write K tile (coalesced float4) ----
#pragma unroll
    for (int i = 0; i < 8; i++) {
        float* orow = out + (size_t)rows[i] * NROWS;
        float4 o0 = make_float4(acc[i][0], acc[i][1], acc[i][2], acc[i][3]);
        float4 o1 = make_float4(acc[i][4], acc[i][5], acc[i][6], acc[i][7]);
        *reinterpret_cast<float4*>(orow + cb + tx * 4) = o0;
        *reinterpret_cast<float4*>(orow + cb + 64 + tx * 4) = o1;
    }
}

// ---------------------------------------------------------------------------
// k_dref: Dref[i] = (sum_ct P1[ct][i])^(-t)
// ---------------------------------------------------------------------------
__global__ void k_dref(const float* __restrict__ ltp) {
    int i = blockIdx.x * blockDim.x + threadIdx.x;
    if (i >= NROWS) return;
    float s = 0.0f;
#pragma unroll 8
    for (int c = 0; c < NCT; c++) s += g_P1[(size_t)c * NROWS + i];
    float t = softplus_f(__ldg(ltp));
    g_Dref[i] = expf(-t * logf(s));
}

// ---------------------------------------------------------------------------
// k_bcol: S2r[row] = sum_j Wr[row][j]*Dref[j]; bcol = Dref * rsqrt(Dref*S2r)
// ---------------------------------------------------------------------------
__global__ void k_bcol(const float* __restrict__ W) {
    int row = blockIdx.x;
    int tid = threadIdx.x;
    const float4* w4 = reinterpret_cast<const float4*>(W + (size_t)row * NROWS);
    const float4* d4 = reinterpret_cast<const float4*>(g_Dref);
    float s = 0.0f;
    for (int j = tid; j < NROWS / 4; j += 256) {
        float4 wv = w4[j];
        float4 dv = d4[j];
        s += wv.x * dv.x + wv.y * dv.y + wv.z * dv.z + wv.w * dv.w;
    }
    __shared__ float red[256];
    red[tid] = s;
    __syncthreads();
#pragma unroll
    for (int o = 128; o > 0; o >>= 1) {
        if (tid < o) red[tid] += red[tid + o];
        __syncthreads();
    }
    if (tid == 0) {
        float dr = g_Dref[row];
        g_bcol[row] = dr * rsqrtf(dr * red[0]);
    }
}

// ---------------------------------------------------------------------------
// k_arow: Dx = (sum P1)^(-t);  arow = Dx * rsqrt(Dx * sum P2)
// ---------------------------------------------------------------------------
__global__ void k_arow(const float* __restrict__ ltp) {
    int i = blockIdx.x * blockDim.x + threadIdx.x;
    if (i >= NROWS) return;
    float s1 = 0.0f, s2 = 0.0f;
#pragma unroll 8
    for (int c = 0; c < NCT; c++) {
        s1 += g_P1[(size_t)c * NROWS + i];
        s2 += g_P2[(size_t)c * NROWS + i];
    }
    float t = softplus_f(__ldg(ltp));
    float dx = expf(-t * logf(s1));
    g_arow[i] = dx * rsqrtf(dx * s2);
}

// ---------------------------------------------------------------------------
// k_scale: out[i][j] *= arow[i] * bcol[j]   (in place, float4)
// ---------------------------------------------------------------------------
__global__ void k_scale(float* __restrict__ out) {
    size_t idx = (size_t)blockIdx.x * blockDim.x + threadIdx.x; // float4 index
    int row = (int)(idx >> 11);        // / (8192/4)
    int c4 = (int)(idx & 2047);
    float a = g_arow[row];
    float4 b = reinterpret_cast<const float4*>(g_bcol)[c4];
    float4* p = reinterpret_cast<float4*>(out) + idx;
    float4 vv = *p;
    vv.x *= a * b.x;
    vv.y *= a * b.y;
    vv.z *= a * b.z;
    vv.w *= a * b.w;
    *p = vv;
}

// ---------------------------------------------------------------------------
extern "C" void kernel_launch(void* const* d_in, const int* in_sizes, int n_in,
                              void* d_out, int out_size) {
    const float* X    = (const float*)d_in[0];
    const float* Xref = (const float*)d_in[1];
    const float* lep  = (const float*)d_in[2];
    const float* ltp  = (const float*)d_in[3];
    float* out = (float*)d_out;

    dim3 evalGrid(NCT, NROWS / 128);

    // per-row -c2*||x||^2 terms
    k_prep<<<NROWS / 256, 256>>>(X, Xref, lep);

    // reference pass: Wr into out, row sums
    k_eval<false><<<evalGrid, 256>>>(Xref, Xref, lep, out);
    k_dref<<<NROWS / 256, 256>>>(ltp);
    k_bcol<<<NROWS, 256>>>(out);

    // cross pass: K into out, S1x + S2x
    k_eval<true><<<evalGrid, 256>>>(X, Xref, lep, out);
    k_arow<<<NROWS / 256, 256>>>(ltp);

    // final elementwise scaling in place
    k_scale<<<(NROWS * (NROWS / 4)) / 256, 256>>>(out);
}

// round 2
// speedup vs baseline: 1.4212x; 1.4212x over previous
#include <cuda_runtime.h>
#include <cstdint>

#define NROWS 8192
#define DIM   16
#define NCT   64   // number of 128-wide column tiles

// ---- device scratch (static, no allocation) ----
__device__ float g_P1[NCT * NROWS];
__device__ float g_P2[NCT * NROWS];
__device__ float g_uX[NROWS];
__device__ float g_uR[NROWS];
__device__ float g_Dref[NROWS];
__device__ float g_bcol[NROWS];
__device__ float g_arow[NROWS];

#define LOG2E 1.4426950408889634f

__device__ __forceinline__ float ex2_approx(float x) {
    float r;
    asm("ex2.approx.f32 %0, %1;" : "=f"(r) : "f"(x));
    return r;
}

__device__ __forceinline__ float softplus_f(float x) {
    return log1pf(expf(x));
}

__device__ __forceinline__ unsigned long long ffma2(unsigned long long a,
                                                    unsigned long long b,
                                                    unsigned long long c) {
    unsigned long long d;
    asm("fma.rn.f32x2 %0, %1, %2, %3;" : "=l"(d) : "l"(a), "l"(b), "l"(c));
    return d;
}

__device__ __forceinline__ void unpack2(unsigned long long v, float& lo, float& hi) {
    asm("mov.b64 {%0, %1}, %2;" : "=f"(lo), "=f"(hi) : "l"(v));
}

// ---------------------------------------------------------------------------
// k_prep: u[i] = -c2 * ||row_i||^2 for X and Xref, c2 = log2(e)/(4*eps)
// ---------------------------------------------------------------------------
__global__ void k_prep(const float* __restrict__ X,
                       const float* __restrict__ Xref,
                       const float* __restrict__ lep) {
    int i = blockIdx.x * blockDim.x + threadIdx.x;
    if (i >= NROWS) return;
    float eps = softplus_f(__ldg(lep));
    float c2 = LOG2E / (4.0f * eps);

    const float4* x4 = reinterpret_cast<const float4*>(X + (size_t)i * DIM);
    float s = 0.0f;
#pragma unroll
    for (int q = 0; q < 4; q++) {
        float4 v = x4[q];
        s += v.x * v.x + v.y * v.y + v.z * v.z + v.w * v.w;
    }
    g_uX[i] = -c2 * s;

    const float4* r4 = reinterpret_cast<const float4*>(Xref + (size_t)i * DIM);
    s = 0.0f;
#pragma unroll
    for (int q = 0; q < 4; q++) {
        float4 v = r4[q];
        s += v.x * v.x + v.y * v.y + v.z * v.z + v.w * v.w;
    }
    g_uR[i] = -c2 * s;
}

// ---------------------------------------------------------------------------
// eval modes
//  REF_SUM : symmetric (Xref x Xref), row sums of K -> P1 (direct + transposed)
//  REF_W   : symmetric, Dref-weighted sums -> P2 (direct + transposed)
//  X_SUM   : full (X x Xref), s1=sum K -> P1, s2=sum K*Dref -> P2
//  X_WRITE : full, out = arow_i * K * bcol_j   (the only pass that writes out)
// ---------------------------------------------------------------------------
#define M_REF_SUM 0
#define M_REF_W   1
#define M_X_SUM   2
#define M_X_WRITE 3

template <int MODE>
__global__ void __launch_bounds__(256, 2)
k_eval(const float* __restrict__ A,
       const float* __restrict__ B,
       const float* __restrict__ lep,
       float* __restrict__ out) {
    constexpr bool SYM = (MODE == M_REF_SUM || MODE == M_REF_W);

    const int bx = blockIdx.x;   // column tile
    const int by = blockIdx.y;   // row tile
    if (SYM && by > bx) return;  // upper triangle only
    const bool offdiag = SYM && (by != bx);

    __shared__ float2 As2[DIM][128];        // (a,a) duplicated pairs, 16KB
    __shared__ float  Bs[DIM][128];         // scalar, 8KB
    __shared__ float  colpart[16][128];     // column-sum partials, 8KB

    const int tid = threadIdx.x;
    const int tx = tid & 15;
    const int ty = tid >> 4;
    const int rb = by * 128;
    const int cb = bx * 128;

    // ---- load tiles (k-major in smem), A duplicated into pairs ----
    {
        int r = tid >> 1;          // 0..127
        int f = (tid & 1) * 2;     // float4 index 0 or 2
        const float4* ap = reinterpret_cast<const float4*>(A + (size_t)(rb + r) * DIM);
        const float4* bp = reinterpret_cast<const float4*>(B + (size_t)(cb + r) * DIM);
#pragma unroll
        for (int q = 0; q < 2; q++) {
            float4 va = ap[f + q];
            float4 vb = bp[f + q];
            int k0 = (f + q) * 4;
            As2[k0 + 0][r] = make_float2(va.x, va.x);
            As2[k0 + 1][r] = make_float2(va.y, va.y);
            As2[k0 + 2][r] = make_float2(va.z, va.z);
            As2[k0 + 3][r] = make_float2(va.w, va.w);
            Bs[k0 + 0][r] = vb.x; Bs[k0 + 1][r] = vb.y;
            Bs[k0 + 2][r] = vb.z; Bs[k0 + 3][r] = vb.w;
        }
    }
    __syncthreads();

    // ---- packed 8x8 register tile (acc2[i][jp] = two adjacent j columns) ----
    unsigned long long acc2[8][4];
#pragma unroll
    for (int i = 0; i < 8; i++)
#pragma unroll
        for (int jp = 0; jp < 4; jp++) acc2[i][jp] = 0ULL;

#pragma unroll
    for (int k = 0; k < DIM; k++) {
        const ulonglong2* a0p = reinterpret_cast<const ulonglong2*>(&As2[k][ty * 4]);
        const ulonglong2* a1p = reinterpret_cast<const ulonglong2*>(&As2[k][64 + ty * 4]);
        ulonglong2 a01 = a0p[0], a23 = a0p[1];
        ulonglong2 a45 = a1p[0], a67 = a1p[1];
        unsigned long long av[8] = {a01.x, a01.y, a23.x, a23.y,
                                    a45.x, a45.y, a67.x, a67.y};
        ulonglong2 b01 = *reinterpret_cast<const ulonglong2*>(&Bs[k][tx * 4]);
        ulonglong2 b23 = *reinterpret_cast<const ulonglong2*>(&Bs[k][64 + tx * 4]);
        unsigned long long bv[4] = {b01.x, b01.y, b23.x, b23.y};
#pragma unroll
        for (int i = 0; i < 8; i++)
#pragma unroll
            for (int jp = 0; jp < 4; jp++)
                acc2[i][jp] = ffma2(av[i], bv[jp], acc2[i][jp]);
    }

    // ---- epilogue ----
    float eps = softplus_f(__ldg(lep));
    float twoc2 = 2.0f * (LOG2E / (4.0f * eps));

    int rows[8], cols[8];
    float u[8], v[8];
    float wrow[8], wcol[8];
    float a_s[8], b_s[8];
#pragma unroll
    for (int i = 0; i < 8; i++) {
        int m = (i < 4) ? (ty * 4 + i) : (64 + ty * 4 + (i - 4));
        rows[i] = rb + m;
        u[i] = (MODE >= M_X_SUM ? g_uX : g_uR)[rows[i]];
        if (MODE == M_REF_W) wrow[i] = g_Dref[rows[i]];
        if (MODE == M_X_WRITE) a_s[i] = g_arow[rows[i]];
    }
#pragma unroll
    for (int j = 0; j < 8; j++) {
        int n = (j < 4) ? (tx * 4 + j) : (64 + tx * 4 + (j - 4));
        cols[j] = cb + n;
        v[j] = g_uR[cols[j]];
        if (MODE == M_REF_W || MODE == M_X_SUM) wcol[j] = g_Dref[cols[j]];
        if (MODE == M_X_WRITE) b_s[j] = g_bcol[cols[j]];
    }

    float s1[8], s2[8], csum[8];
#pragma unroll
    for (int i = 0; i < 8; i++) { s1[i] = 0.0f; s2[i] = 0.0f; csum[i] = 0.0f; }

#pragma unroll
    for (int i = 0; i < 8; i++) {
        float kv8[8];
#pragma unroll
        for (int jp = 0; jp < 4; jp++) {
            float g0, g1;
            unpack2(acc2[i][jp], g0, g1);
            int j0 = jp * 2, j1 = jp * 2 + 1;
            float arg0 = fmaf(g0, twoc2, u[i] + v[j0]);
            float arg1 = fmaf(g1, twoc2, u[i] + v[j1]);
            kv8[j0] = ex2_approx(arg0);
            kv8[j1] = ex2_approx(arg1);
        }
#pragma unroll
        for (int j = 0; j < 8; j++) {
            float kv = kv8[j];
            if (MODE == M_REF_SUM) {
                s1[i] += kv;
                csum[j] += kv;                       // transposed row sums
            } else if (MODE == M_REF_W) {
                s1[i] = fmaf(kv, wcol[j], s1[i]);    // sum_j K * Dref_j
                csum[j] = fmaf(kv, wrow[i], csum[j]); // sum_i K * Dref_i
            } else if (MODE == M_X_SUM) {
                s1[i] += kv;
                s2[i] = fmaf(kv, wcol[j], s2[i]);
            }
        }
        if (MODE == M_X_WRITE) {
            float* orow = out + (size_t)rows[i] * NROWS;
            float ai = a_s[i];
            float4 o0 = make_float4(ai * kv8[0] * b_s[0], ai * kv8[1] * b_s[1],
                                    ai * kv8[2] * b_s[2], ai * kv8[3] * b_s[3]);
            float4 o1 = make_float4(ai * kv8[4] * b_s[4], ai * kv8[5] * b_s[5],
                                    ai * kv8[6] * b_s[6], ai * kv8[7] * b_s[7]);
            *reinterpret_cast<float4*>(orow + cb + tx * 4) = o0;
            *reinterpret_cast<float4*>(orow + cb + 64 + tx * 4) = o1;
        }
    }

    // ---- row-sum reduction across the 16 tx lanes sharing each row ----
    if (MODE != M_X_WRITE) {
#pragma unroll
        for (int i = 0; i < 8; i++) {
            float t1 = s1[i];
            float t2 = (MODE == M_X_SUM) ? s2[i] : 0.0f;
#pragma unroll
            for (int off = 8; off >= 1; off >>= 1) {
                t1 += __shfl_xor_sync(0xffffffffu, t1, off);
                if (MODE == M_X_SUM) t2 += __shfl_xor_sync(0xffffffffu, t2, off);
            }
            if (tx == 0) {
                if (MODE == M_REF_SUM) g_P1[(size_t)bx * NROWS + rows[i]] = t1;
                if (MODE == M_REF_W)   g_P2[(size_t)bx * NROWS + rows[i]] = t1;
                if (MODE == M_X_SUM) {
                    g_P1[(size_t)bx * NROWS + rows[i]] = t1;
                    g_P2[(size_t)bx * NROWS + rows[i]] = t2;
                }
            }
        }
    }

    // ---- transposed (column) sums for off-diagonal symmetric tiles ----
    if (SYM) {
        if (offdiag) {
#pragma unroll
            for (int j = 0; j < 8; j++) {
                int n = (j < 4) ? (tx * 4 + j) : (64 + tx * 4 + (j - 4));
                colpart[ty][n] = csum[j];
            }
            __syncthreads();
            if (tid < 128) {
                float s = 0.0f;
#pragma unroll
                for (int q = 0; q < 16; q++) s += colpart[q][tid];
                // contribution of rows-in-by-tile to the row (cb + tid),
                // stored under column-tile index `by`
                if (MODE == M_REF_SUM) g_P1[(size_t)by * NROWS + cb + tid] = s;
                else                   g_P2[(size_t)by * NROWS + cb + tid] = s;
            }
        }
    }
}

// ---------------------------------------------------------------------------
// k_dref: Dref[i] = (sum_ct P1[ct][i])^(-t)
// ---------------------------------------------------------------------------
__global__ void k_dref(const float* __restrict__ ltp) {
    int i = blockIdx.x * blockDim.x + threadIdx.x;
    if (i >= NROWS) return;
    float s = 0.0f;
#pragma unroll 8
    for (int c = 0; c < NCT; c++) s += g_P1[(size_t)c * NROWS + i];
    float t = softplus_f(__ldg(ltp));
    g_Dref[i] = expf(-t * logf(s));
}

// ---------------------------------------------------------------------------
// k_bfin: T_i = sum P2;  bcol_i = Dref_i * rsqrt(Dref_i * T_i)
// ---------------------------------------------------------------------------
__global__ void k_bfin() {
    int i = blockIdx.x * blockDim.x + threadIdx.x;
    if (i >= NROWS) return;
    float T = 0.0f;
#pragma unroll 8
    for (int c = 0; c < NCT; c++) T += g_P2[(size_t)c * NROWS + i];
    float dr = g_Dref[i];
    g_bcol[i] = dr * rsqrtf(dr * T);
}

// ---------------------------------------------------------------------------
// k_arow: Dx = (sum P1)^(-t);  U = sum P2;  arow = Dx * rsqrt(Dx * U)
// ---------------------------------------------------------------------------
__global__ void k_arow(const float* __restrict__ ltp) {
    int i = blockIdx.x * blockDim.x + threadIdx.x;
    if (i >= NROWS) return;
    float s1 = 0.0f, s2 = 0.0f;
#pragma unroll 8
    for (int c = 0; c < NCT; c++) {
        s1 += g_P1[(size_t)c * NROWS + i];
        s2 += g_P2[(size_t)c * NROWS + i];
    }
    float t = softplus_f(__ldg(ltp));
    float dx = expf(-t * logf(s1));
    g_arow[i] = dx * rsqrtf(dx * s2);
}

// ---------------------------------------------------------------------------
extern "C" void kernel_launch(void* const* d_in, const int* in_sizes, int n_in,
                              void* d_out, int out_size) {
    const float* X    = (const float*)d_in[0];
    const float* Xref = (const float*)d_in[1];
    const float* lep  = (const float*)d_in[2];
    const float* ltp  = (const float*)d_in[3];
    float* out = (float*)d_out;

    dim3 evalGrid(NCT, NROWS / 128);

    // per-row -c2*||x||^2 terms
    k_prep<<<NROWS / 256, 256>>>(X, Xref, lep);

    // reference branch: two symmetric half-passes, no Wr materialization
    k_eval<M_REF_SUM><<<evalGrid, 256>>>(Xref, Xref, lep, nullptr);
    k_dref<<<NROWS / 256, 256>>>(ltp);
    k_eval<M_REF_W><<<evalGrid, 256>>>(Xref, Xref, lep, nullptr);
    k_bfin<<<NROWS / 256, 256>>>();

    // cross branch: sums pass, then fused write of a_i * K * b_j
    k_eval<M_X_SUM><<<evalGrid, 256>>>(X, Xref, lep, nullptr);
    k_arow<<<NROWS / 256, 256>>>(ltp);
    k_eval<M_X_WRITE><<<evalGrid, 256>>>(X, Xref, lep, out);
}

// round 3
// speedup vs baseline: 1.5401x; 1.0837x over previous
#include <cuda_runtime.h>
#include <cstdint>

#define NROWS 8192
#define DIM   16
#define NCT   64                 // number of 128-wide column tiles
#define NTRI  (NCT * (NCT + 1) / 2)   // 2080 upper-triangle tiles

typedef unsigned long long ull;

// ---- device scratch (static, no allocation) ----
__device__ float g_P1[NCT * NROWS];
__device__ float g_P2[NCT * NROWS];
__device__ float g_uX[NROWS];
__device__ float g_uR[NROWS];
__device__ float g_Dref[NROWS];
__device__ float g_bcol[NROWS];
__device__ float g_arow[NROWS];

#define LOG2E 1.4426950408889634f

__device__ __forceinline__ float ex2_approx(float x) {
    float r;
    asm("ex2.approx.f32 %0, %1;" : "=f"(r) : "f"(x));
    return r;
}

__device__ __forceinline__ float softplus_f(float x) {
    return log1pf(expf(x));
}

__device__ __forceinline__ ull ffma2(ull a, ull b, ull c) {
    ull d;
    asm("fma.rn.f32x2 %0, %1, %2, %3;" : "=l"(d) : "l"(a), "l"(b), "l"(c));
    return d;
}

__device__ __forceinline__ void unpack2(ull v, float& lo, float& hi) {
    asm("mov.b64 {%0, %1}, %2;" : "=f"(lo), "=f"(hi) : "l"(v));
}

__device__ __forceinline__ ull swap2(ull v) {
    float lo, hi;
    asm("mov.b64 {%0, %1}, %2;" : "=f"(lo), "=f"(hi) : "l"(v));
    ull r;
    asm("mov.b64 %0, {%1, %2};" : "=l"(r) : "f"(hi), "f"(lo));
    return r;
}

// ---------------------------------------------------------------------------
// k_prep: u[i] = -c2 * ||row_i||^2 for X and Xref, c2 = log2(e)/(4*eps)
// ---------------------------------------------------------------------------
__global__ void k_prep(const float* __restrict__ X,
                       const float* __restrict__ Xref,
                       const float* __restrict__ lep) {
    int i = blockIdx.x * blockDim.x + threadIdx.x;
    if (i >= NROWS) return;
    float eps = softplus_f(__ldg(lep));
    float c2 = LOG2E / (4.0f * eps);

    const float4* x4 = reinterpret_cast<const float4*>(X + (size_t)i * DIM);
    float s = 0.0f;
#pragma unroll
    for (int q = 0; q < 4; q++) {
        float4 v = x4[q];
        s += v.x * v.x + v.y * v.y + v.z * v.z + v.w * v.w;
    }
    g_uX[i] = -c2 * s;

    const float4* r4 = reinterpret_cast<const float4*>(Xref + (size_t)i * DIM);
    s = 0.0f;
#pragma unroll
    for (int q = 0; q < 4; q++) {
        float4 v = r4[q];
        s += v.x * v.x + v.y * v.y + v.z * v.z + v.w * v.w;
    }
    g_uR[i] = -c2 * s;
}

// ---------------------------------------------------------------------------
// eval modes
// ---------------------------------------------------------------------------
#define M_REF_SUM 0
#define M_REF_W   1
#define M_X_SUM   2
#define M_X_WRITE 3

template <int MODE>
__global__ void __launch_bounds__(256, 2)
k_eval(const float* __restrict__ A,
       const float* __restrict__ B,
       const float* __restrict__ lep,
       float* __restrict__ out) {
    constexpr bool SYM = (MODE == M_REF_SUM || MODE == M_REF_W);

    int bx, by;
    if (SYM) {
        // linear upper-triangle decode: blocks only where by <= bx
        int l = blockIdx.x;
        bx = (int)((sqrtf(8.0f * (float)l + 1.0f) - 1.0f) * 0.5f);
        while ((bx * (bx + 1)) / 2 > l) bx--;
        while (((bx + 1) * (bx + 2)) / 2 <= l) bx++;
        by = l - (bx * (bx + 1)) / 2;
    } else {
        bx = blockIdx.x;
        by = blockIdx.y;
    }
    const bool offdiag = SYM && (by != bx);

    __shared__ float As[DIM][128];      // 8KB, scalar
    __shared__ float Bs[DIM][128];      // 8KB, scalar
    __shared__ float colpart[16][128];  // 8KB, column-sum partials

    const int tid = threadIdx.x;
    const int tx = tid & 15;
    const int ty = tid >> 4;
    const int rb = by * 128;
    const int cb = bx * 128;
    const int m0 = ty * 4, m1 = 64 + ty * 4;
    const int n0 = tx * 4, n1 = 64 + tx * 4;

    // ---- load tiles (k-major in smem) ----
    {
        int r = tid >> 1;          // 0..127
        int f = (tid & 1) * 2;     // float4 index 0 or 2
        const float4* ap = reinterpret_cast<const float4*>(A + (size_t)(rb + r) * DIM);
        const float4* bp = reinterpret_cast<const float4*>(B + (size_t)(cb + r) * DIM);
#pragma unroll
        for (int q = 0; q < 2; q++) {
            float4 va = ap[f + q];
            float4 vb = bp[f + q];
            int k0 = (f + q) * 4;
            As[k0 + 0][r] = va.x; As[k0 + 1][r] = va.y;
            As[k0 + 2][r] = va.z; As[k0 + 3][r] = va.w;
            Bs[k0 + 0][r] = vb.x; Bs[k0 + 1][r] = vb.y;
            Bs[k0 + 2][r] = vb.z; Bs[k0 + 3][r] = vb.w;
        }
    }
    __syncthreads();

    // ---- parity-packed 8x8 register tile ----
    // accd[rp][cp] = ( g[r_even][c_even], g[r_odd][c_odd] )
    // acca[rp][cp] = ( g[r_even][c_odd],  g[r_odd][c_even] )
    ull accd[4][4], acca[4][4];
#pragma unroll
    for (int rp = 0; rp < 4; rp++)
#pragma unroll
        for (int cp = 0; cp < 4; cp++) { accd[rp][cp] = 0ULL; acca[rp][cp] = 0ULL; }

#pragma unroll
    for (int k = 0; k < DIM; k++) {
        ulonglong2 aA = *reinterpret_cast<const ulonglong2*>(&As[k][m0]);
        ulonglong2 aB = *reinterpret_cast<const ulonglong2*>(&As[k][m1]);
        ulonglong2 bA = *reinterpret_cast<const ulonglong2*>(&Bs[k][n0]);
        ulonglong2 bB = *reinterpret_cast<const ulonglong2*>(&Bs[k][n1]);
        ull ra[4] = {aA.x, aA.y, aB.x, aB.y};
        ull cbp[4] = {bA.x, bA.y, bB.x, bB.y};
        ull csp[4] = {swap2(cbp[0]), swap2(cbp[1]), swap2(cbp[2]), swap2(cbp[3])};
#pragma unroll
        for (int rp = 0; rp < 4; rp++)
#pragma unroll
            for (int cp = 0; cp < 4; cp++) {
                accd[rp][cp] = ffma2(ra[rp], cbp[cp], accd[rp][cp]);
                acca[rp][cp] = ffma2(ra[rp], csp[cp], acca[rp][cp]);
            }
    }

    // ---- epilogue ----
    float eps = softplus_f(__ldg(lep));
    float twoc2 = 2.0f * (LOG2E / (4.0f * eps));

    int rows[8], cols[8];
    float u[8], v[8];
    float wrow[8], wcol[8];
    float a_s[8], b_s[8];
#pragma unroll
    for (int i = 0; i < 8; i++) {
        int m = (i < 4) ? (m0 + i) : (m1 + (i - 4));
        rows[i] = rb + m;
        u[i] = (MODE >= M_X_SUM ? g_uX : g_uR)[rows[i]];
        if (MODE == M_REF_W) wrow[i] = g_Dref[rows[i]];
        if (MODE == M_X_WRITE) a_s[i] = g_arow[rows[i]];
    }
#pragma unroll
    for (int j = 0; j < 8; j++) {
        int n = (j < 4) ? (n0 + j) : (n1 + (j - 4));
        cols[j] = cb + n;
        v[j] = g_uR[cols[j]];
        if (MODE == M_REF_W || MODE == M_X_SUM) wcol[j] = g_Dref[cols[j]];
        if (MODE == M_X_WRITE) b_s[j] = g_bcol[cols[j]];
    }

    float s1[8], s2[8], csum[8];
#pragma unroll
    for (int i = 0; i < 8; i++) { s1[i] = 0.0f; s2[i] = 0.0f; csum[i] = 0.0f; }

    // process per row-pair; acc registers die as we go
#pragma unroll
    for (int rp = 0; rp < 4; rp++) {
        const int i0 = 2 * rp, i1 = 2 * rp + 1;
        float kv0[8], kv1[8];
#pragma unroll
        for (int cp = 0; cp < 4; cp++) {
            const int j0 = 2 * cp, j1 = 2 * cp + 1;
            float d0, d1, a0, a1;
            unpack2(accd[rp][cp], d0, d1);
            unpack2(acca[rp][cp], a0, a1);
            float k00 = ex2_approx(fmaf(d0, twoc2, u[i0] + v[j0]));
            float k11 = ex2_approx(fmaf(d1, twoc2, u[i1] + v[j1]));
            float k01 = ex2_approx(fmaf(a0, twoc2, u[i0] + v[j1]));
            float k10 = ex2_approx(fmaf(a1, twoc2, u[i1] + v[j0]));
            kv0[j0] = k00; kv0[j1] = k01;
            kv1[j0] = k10; kv1[j1] = k11;
        }
#pragma unroll
        for (int j = 0; j < 8; j++) {
            if (MODE == M_REF_SUM) {
                s1[i0] += kv0[j];
                s1[i1] += kv1[j];
                csum[j] += kv0[j] + kv1[j];
            } else if (MODE == M_REF_W) {
                s1[i0] = fmaf(kv0[j], wcol[j], s1[i0]);
                s1[i1] = fmaf(kv1[j], wcol[j], s1[i1]);
                csum[j] = fmaf(kv0[j], wrow[i0], csum[j]);
                csum[j] = fmaf(kv1[j], wrow[i1], csum[j]);
            } else if (MODE == M_X_SUM) {
                s1[i0] += kv0[j];
                s1[i1] += kv1[j];
                s2[i0] = fmaf(kv0[j], wcol[j], s2[i0]);
                s2[i1] = fmaf(kv1[j], wcol[j], s2[i1]);
            }
        }
        if (MODE == M_X_WRITE) {
            float ai0 = a_s[i0], ai1 = a_s[i1];
            float* orow0 = out + (size_t)rows[i0] * NROWS;
            float* orow1 = out + (size_t)rows[i1] * NROWS;
            float4 o;
            o = make_float4(ai0 * kv0[0] * b_s[0], ai0 * kv0[1] * b_s[1],
                            ai0 * kv0[2] * b_s[2], ai0 * kv0[3] * b_s[3]);
            *reinterpret_cast<float4*>(orow0 + cb + n0) = o;
            o = make_float4(ai0 * kv0[4] * b_s[4], ai0 * kv0[5] * b_s[5],
                            ai0 * kv0[6] * b_s[6], ai0 * kv0[7] * b_s[7]);
            *reinterpret_cast<float4*>(orow0 + cb + n1) = o;
            o = make_float4(ai1 * kv1[0] * b_s[0], ai1 * kv1[1] * b_s[1],
                            ai1 * kv1[2] * b_s[2], ai1 * kv1[3] * b_s[3]);
            *reinterpret_cast<float4*>(orow1 + cb + n0) = o;
            o = make_float4(ai1 * kv1[4] * b_s[4], ai1 * kv1[5] * b_s[5],
                            ai1 * kv1[6] * b_s[6], ai1 * kv1[7] * b_s[7]);
            *reinterpret_cast<float4*>(orow1 + cb + n1) = o;
        }
    }

    // ---- row-sum reduction across the 16 tx lanes sharing each row ----
    if (MODE != M_X_WRITE) {
#pragma unroll
        for (int i = 0; i < 8; i++) {
            float t1 = s1[i];
            float t2 = (MODE == M_X_SUM) ? s2[i] : 0.0f;
#pragma unroll
            for (int off = 8; off >= 1; off >>= 1) {
                t1 += __shfl_xor_sync(0xffffffffu, t1, off);
                if (MODE == M_X_SUM) t2 += __shfl_xor_sync(0xffffffffu, t2, off);
            }
            if (tx == 0) {
                if (MODE == M_REF_SUM) g_P1[(size_t)bx * NROWS + rows[i]] = t1;
                if (MODE == M_REF_W)   g_P2[(size_t)bx * NROWS + rows[i]] = t1;
                if (MODE == M_X_SUM) {
                    g_P1[(size_t)bx * NROWS + rows[i]] = t1;
                    g_P2[(size_t)bx * NROWS + rows[i]] = t2;
                }
            }
        }
    }

    // ---- transposed (column) sums for off-diagonal symmetric tiles ----
    if (SYM && offdiag) {
#pragma unroll
        for (int j = 0; j < 8; j++) {
            int n = (j < 4) ? (n0 + j) : (n1 + (j - 4));
            colpart[ty][n] = csum[j];
        }
        __syncthreads();
        if (tid < 128) {
            float s = 0.0f;
#pragma unroll
            for (int q = 0; q < 16; q++) s += colpart[q][tid];
            if (MODE == M_REF_SUM) g_P1[(size_t)by * NROWS + cb + tid] = s;
            else                   g_P2[(size_t)by * NROWS + cb + tid] = s;
        }
    }
}

// ---------------------------------------------------------------------------
// k_dref: Dref[i] = (sum_ct P1[ct][i])^(-t)
// ---------------------------------------------------------------------------
__global__ void k_dref(const float* __restrict__ ltp) {
    int i = blockIdx.x * blockDim.x + threadIdx.x;
    if (i >= NROWS) return;
    float s = 0.0f;
#pragma unroll 8
    for (int c = 0; c < NCT; c++) s += g_P1[(size_t)c * NROWS + i];
    float t = softplus_f(__ldg(ltp));
    g_Dref[i] = expf(-t * logf(s));
}

// ---------------------------------------------------------------------------
// k_bfin: T_i = sum P2;  bcol_i = Dref_i * rsqrt(Dref_i * T_i)
// ---------------------------------------------------------------------------
__global__ void k_bfin() {
    int i = blockIdx.x * blockDim.x + threadIdx.x;
    if (i >= NROWS) return;
    float T = 0.0f;
#pragma unroll 8
    for (int c = 0; c < NCT; c++) T += g_P2[(size_t)c * NROWS + i];
    float dr = g_Dref[i];
    g_bcol[i] = dr * rsqrtf(dr * T);
}

// ---------------------------------------------------------------------------
// k_arow: Dx = (sum P1)^(-t);  U = sum P2;  arow = Dx * rsqrt(Dx * U)
// ---------------------------------------------------------------------------
__global__ void k_arow(const float* __restrict__ ltp) {
    int i = blockIdx.x * blockDim.x + threadIdx.x;
    if (i >= NROWS) return;
    float s1 = 0.0f, s2 = 0.0f;
#pragma unroll 8
    for (int c = 0; c < NCT; c++) {
        s1 += g_P1[(size_t)c * NROWS + i];
        s2 += g_P2[(size_t)c * NROWS + i];
    }
    float t = softplus_f(__ldg(ltp));
    float dx = expf(-t * logf(s1));
    g_arow[i] = dx * rsqrtf(dx * s2);
}

// ---------------------------------------------------------------------------
extern "C" void kernel_launch(void* const* d_in, const int* in_sizes, int n_in,
                              void* d_out, int out_size) {
    const float* X    = (const float*)d_in[0];
    const float* Xref = (const float*)d_in[1];
    const float* lep  = (const float*)d_in[2];
    const float* ltp  = (const float*)d_in[3];
    float* out = (float*)d_out;

    dim3 fullGrid(NCT, NROWS / 128);

    // per-row -c2*||x||^2 terms
    k_prep<<<NROWS / 256, 256>>>(X, Xref, lep);

    // reference branch: two symmetric half-passes (triangle-only grids)
    k_eval<M_REF_SUM><<<NTRI, 256>>>(Xref, Xref, lep, nullptr);
    k_dref<<<NROWS / 256, 256>>>(ltp);
    k_eval<M_REF_W><<<NTRI, 256>>>(Xref, Xref, lep, nullptr);
    k_bfin<<<NROWS / 256, 256>>>();

    // cross branch: sums pass, then fused write of a_i * K * b_j
    k_eval<M_X_SUM><<<fullGrid, 256>>>(X, Xref, lep, nullptr);
    k_arow<<<NROWS / 256, 256>>>(ltp);
    k_eval<M_X_WRITE><<<fullGrid, 256>>>(X, Xref, lep, out);
}

// round 5
// speedup vs baseline: 1.5972x; 1.0371x over previous
#include <cuda_runtime.h>
#include <cuda_bf16.h>
#include <cstdint>

#define NROWS 8192
#define DIM   16
#define NCT   64
#define LOG2E 1.4426950408889634f

// ---- device scratch (static, no allocation) ----
__device__ float g_P1[NCT * NROWS];
__device__ float g_P2[NCT * NROWS];
__device__ float g_Dref[NROWS];
__device__ float g_bcol[NROWS];
__device__ float g_arow[NROWS];

__device__ __forceinline__ float ex2_approx(float x) {
    float r; asm("ex2.approx.f32 %0, %1;" : "=f"(r) : "f"(x)); return r;
}
__device__ __forceinline__ float softplus_f(float x) { return log1pf(expf(x)); }

// d += A(16x16 bf16, row-major) * B(16x8 bf16, col-major)
__device__ __forceinline__ void mma16816(float& d0, float& d1, float& d2, float& d3,
                                         uint32_t a0, uint32_t a1, uint32_t a2, uint32_t a3,
                                         uint32_t b0, uint32_t b1) {
    asm volatile(
        "mma.sync.aligned.m16n8k16.row.col.f32.bf16.bf16.f32 "
        "{%0,%1,%2,%3}, {%4,%5,%6,%7}, {%8,%9}, {%0,%1,%2,%3};"
        : "+f"(d0), "+f"(d1), "+f"(d2), "+f"(d3)
        : "r"(a0), "r"(a1), "r"(a2), "r"(a3), "r"(b0), "r"(b1));
}

// pack two floats into bf16x2 (hi parts) and residual bf16x2 (lo parts)
__device__ __forceinline__ void pack_hilo(float x0, float x1, uint32_t& hw, uint32_t& lw) {
    __nv_bfloat16 h0 = __float2bfloat16(x0);
    __nv_bfloat16 h1 = __float2bfloat16(x1);
    __nv_bfloat16 l0 = __float2bfloat16(x0 - __bfloat162float(h0));
    __nv_bfloat16 l1 = __float2bfloat16(x1 - __bfloat162float(h1));
    hw = (uint32_t)__bfloat16_as_ushort(h0) | ((uint32_t)__bfloat16_as_ushort(h1) << 16);
    lw = (uint32_t)__bfloat16_as_ushort(l0) | ((uint32_t)__bfloat16_as_ushort(l1) << 16);
}

#define M_REF_SUM 0
#define M_REF_W   1
#define M_X_SUM   2
#define M_X_WRITE 3

// ---------------------------------------------------------------------------
// k_eval: 128x128 tile per CTA, 8 warps, warp w owns rows w*16..w*16+15.
// Gram via mma.sync bf16 hi/lo (3 HMMA per 16x8 block), epilogue inline.
// ---------------------------------------------------------------------------
template <int MODE>
__global__ void __launch_bounds__(256, 4)
k_eval(const float* __restrict__ A,
       const float* __restrict__ B,
       const float* __restrict__ lep,
       float* __restrict__ out) {
    __shared__ uint32_t sAhi[128][9], sAlo[128][9];   // kpair-packed bf16x2
    __shared__ uint32_t sBhi[128][9], sBlo[128][9];
    __shared__ float sU[128], sV[128], sW[128], sBc[128];

    const int tid = threadIdx.x;
    const int w = tid >> 5;
    const int lane = tid & 31;
    const int g = lane >> 2;      // 0..7
    const int kq = lane & 3;      // 0..3
    const int rb = blockIdx.y * 128;
    const int cb = blockIdx.x * 128;

    const float eps = softplus_f(__ldg(lep));
    const float c2 = LOG2E / (4.0f * eps);
    const float twoc2 = 2.0f * c2;

    // ---- load + convert tiles: threads 0..127 -> A rows, 128..255 -> B rows ----
    {
        const int r = tid & 127;
        const bool isA = (tid < 128);
        const float* src = isA ? (A + (size_t)(rb + r) * DIM)
                               : (B + (size_t)(cb + r) * DIM);
        const float4* s4 = reinterpret_cast<const float4*>(src);
        float v[16]; float nrm = 0.0f;
#pragma unroll
        for (int q = 0; q < 4; q++) {
            float4 t = s4[q];
            v[4 * q] = t.x; v[4 * q + 1] = t.y; v[4 * q + 2] = t.z; v[4 * q + 3] = t.w;
            nrm += t.x * t.x + t.y * t.y + t.z * t.z + t.w * t.w;
        }
#pragma unroll
        for (int kp = 0; kp < 8; kp++) {
            uint32_t hw, lw;
            pack_hilo(v[2 * kp], v[2 * kp + 1], hw, lw);
            if (isA) { sAhi[r][kp] = hw; sAlo[r][kp] = lw; }
            else     { sBhi[r][kp] = hw; sBlo[r][kp] = lw; }
        }
        if (isA) {
            sU[r] = -c2 * nrm;
        } else {
            sV[r] = -c2 * nrm;
            if (MODE == M_REF_W || MODE == M_X_SUM) sW[r] = g_Dref[cb + r];
            if (MODE == M_X_WRITE) sBc[r] = g_bcol[cb + r];
        }
    }
    __syncthreads();

    // ---- A fragments for this warp (rows w*16+g and +8) ----
    const int ra0 = w * 16 + g;
    const int ra1 = ra0 + 8;
    const uint32_t ahi0 = sAhi[ra0][kq], ahi1 = sAhi[ra1][kq];
    const uint32_t ahi2 = sAhi[ra0][kq + 4], ahi3 = sAhi[ra1][kq + 4];
    const uint32_t alo0 = sAlo[ra0][kq], alo1 = sAlo[ra1][kq];
    const uint32_t alo2 = sAlo[ra0][kq + 4], alo3 = sAlo[ra1][kq + 4];
    const float u0 = sU[ra0], u1 = sU[ra1];

    float aval0 = 0.0f, aval1 = 0.0f;
    if (MODE == M_X_WRITE) {
        aval0 = g_arow[rb + ra0];
        aval1 = g_arow[rb + ra1];
    }

    float s1_0 = 0.0f, s1_1 = 0.0f, s2_0 = 0.0f, s2_1 = 0.0f;

#pragma unroll
    for (int cb8 = 0; cb8 < 16; cb8++) {
        const int n = cb8 * 8 + g;          // B row (= output col owner for b-frag)
        const uint32_t bhi0 = sBhi[n][kq], bhi1 = sBhi[n][kq + 4];
        const uint32_t blo0 = sBlo[n][kq], blo1 = sBlo[n][kq + 4];

        float d0 = 0.0f, d1 = 0.0f, d2 = 0.0f, d3 = 0.0f;
        mma16816(d0, d1, d2, d3, ahi0, ahi1, ahi2, ahi3, bhi0, bhi1);
        mma16816(d0, d1, d2, d3, ahi0, ahi1, ahi2, ahi3, blo0, blo1);
        mma16816(d0, d1, d2, d3, alo0, alo1, alo2, alo3, bhi0, bhi1);

        const int cl = cb8 * 8 + 2 * kq;    // local col of d0/d2; d1/d3 at cl+1
        const float2 vv = *reinterpret_cast<const float2*>(&sV[cl]);

        float k00 = ex2_approx(fminf(fmaf(d0, twoc2, u0 + vv.x), 0.0f));
        float k01 = ex2_approx(fminf(fmaf(d1, twoc2, u0 + vv.y), 0.0f));
        float k10 = ex2_approx(fminf(fmaf(d2, twoc2, u1 + vv.x), 0.0f));
        float k11 = ex2_approx(fminf(fmaf(d3, twoc2, u1 + vv.y), 0.0f));

        if (MODE == M_REF_SUM) {
            s1_0 += k00 + k01;
            s1_1 += k10 + k11;
        } else if (MODE == M_REF_W) {
            const float2 ww = *reinterpret_cast<const float2*>(&sW[cl]);
            s1_0 = fmaf(k00, ww.x, fmaf(k01, ww.y, s1_0));
            s1_1 = fmaf(k10, ww.x, fmaf(k11, ww.y, s1_1));
        } else if (MODE == M_X_SUM) {
            const float2 ww = *reinterpret_cast<const float2*>(&sW[cl]);
            s1_0 += k00 + k01;
            s1_1 += k10 + k11;
            s2_0 = fmaf(k00, ww.x, fmaf(k01, ww.y, s2_0));
            s2_1 = fmaf(k10, ww.x, fmaf(k11, ww.y, s2_1));
        } else { // M_X_WRITE
            const float2 bc = *reinterpret_cast<const float2*>(&sBc[cl]);
            float2 o0 = make_float2(aval0 * k00 * bc.x, aval0 * k01 * bc.y);
            float2 o1 = make_float2(aval1 * k10 * bc.x, aval1 * k11 * bc.y);
            *reinterpret_cast<float2*>(out + (size_t)(rb + ra0) * NROWS + cb + cl) = o0;
            *reinterpret_cast<float2*>(out + (size_t)(rb + ra1) * NROWS + cb + cl) = o1;
        }
    }

    // ---- reduce across the 4 kq lanes of each group, write partial sums ----
    if (MODE != M_X_WRITE) {
#pragma unroll
        for (int off = 1; off <= 2; off <<= 1) {
            s1_0 += __shfl_xor_sync(0xffffffffu, s1_0, off);
            s1_1 += __shfl_xor_sync(0xffffffffu, s1_1, off);
            if (MODE == M_X_SUM) {
                s2_0 += __shfl_xor_sync(0xffffffffu, s2_0, off);
                s2_1 += __shfl_xor_sync(0xffffffffu, s2_1, off);
            }
        }
        if (kq == 0) {
            const size_t base = (size_t)blockIdx.x * NROWS + rb;
            if (MODE == M_REF_SUM) {
                g_P1[base + ra0] = s1_0;
                g_P1[base + ra1] = s1_1;
            } else if (MODE == M_REF_W) {
                g_P2[base + ra0] = s1_0;
                g_P2[base + ra1] = s1_1;
            } else { // M_X_SUM
                g_P1[base + ra0] = s1_0;
                g_P1[base + ra1] = s1_1;
                g_P2[base + ra0] = s2_0;
                g_P2[base + ra1] = s2_1;
            }
        }
    }
}

// ---------------------------------------------------------------------------
__global__ void k_dref(const float* __restrict__ ltp) {
    int i = blockIdx.x * blockDim.x + threadIdx.x;
    if (i >= NROWS) return;
    float s = 0.0f;
#pragma unroll 8
    for (int c = 0; c < NCT; c++) s += g_P1[(size_t)c * NROWS + i];
    float t = softplus_f(__ldg(ltp));
    g_Dref[i] = expf(-t * logf(s));
}

__global__ void k_bfin() {
    int i = blockIdx.x * blockDim.x + threadIdx.x;
    if (i >= NROWS) return;
    float T = 0.0f;
#pragma unroll 8
    for (int c = 0; c < NCT; c++) T += g_P2[(size_t)c * NROWS + i];
    float dr = g_Dref[i];
    g_bcol[i] = dr * rsqrtf(dr * T);
}

__global__ void k_arow(const float* __restrict__ ltp) {
    int i = blockIdx.x * blockDim.x + threadIdx.x;
    if (i >= NROWS) return;
    float s1 = 0.0f, s2 = 0.0f;
#pragma unroll 8
    for (int c = 0; c < NCT; c++) {
        s1 += g_P1[(size_t)c * NROWS + i];
        s2 += g_P2[(size_t)c * NROWS + i];
    }
    float t = softplus_f(__ldg(ltp));
    float dx = expf(-t * logf(s1));
    g_arow[i] = dx * rsqrtf(dx * s2);
}

// ---------------------------------------------------------------------------
extern "C" void kernel_launch(void* const* d_in, const int* in_sizes, int n_in,
                              void* d_out, int out_size) {
    const float* X    = (const float*)d_in[0];
    const float* Xref = (const float*)d_in[1];
    const float* lep  = (const float*)d_in[2];
    const float* ltp  = (const float*)d_in[3];
    float* out = (float*)d_out;

    dim3 grid(NCT, NCT);

    k_eval<M_REF_SUM><<<grid, 256>>>(Xref, Xref, lep, nullptr);
    k_dref<<<NROWS / 256, 256>>>(ltp);
    k_eval<M_REF_W><<<grid, 256>>>(Xref, Xref, lep, nullptr);
    k_bfin<<<NROWS / 256, 256>>>();
    k_eval<M_X_SUM><<<grid, 256>>>(X, Xref, lep, nullptr);
    k_arow<<<NROWS / 256, 256>>>(ltp);
    k_eval<M_X_WRITE><<<grid, 256>>>(X, Xref, lep, out);
}